// round 6
// baseline (speedup 1.0000x reference)
#include <cuda_runtime.h>
#include <cuda_bf16.h>
#include <math.h>
#include <stdint.h>

// Problem constants
#define BB 2
#define TT 2048
#define DD 2048
#define HH 16
#define DKq 64
#define DVv 128
#define RR 16
#define CC 64
#define NCC 32
#define MM (BB*TT)          // 4096
#define NQK (HH*DKq)        // 1024
#define NV  (HH*DVv)        // 2048
#define GLN_INV (1.0f/16.0f)
#define EPSL 1e-5f

// ---------------- scratch (device globals, no allocs allowed) ----------------
__device__ float g_q [MM*NQK];
__device__ float g_k [MM*NQK];
__device__ float g_v [MM*NV];
__device__ float g_gk[MM*NQK];
__device__ float g_r1[MM*RR];
__device__ float g_r2[MM*RR];
__device__ float g_g [MM*NV];
__device__ float g_o [MM*NV];
__device__ float g_hsr[MM*DD];     // tf32-rounded + permuted hs
__device__ float g_wqr[DD*NQK];    // transposed [N][K] + permuted + rounded
__device__ float g_wkr[DD*NQK];
__device__ float g_wvr[DD*NV];
__device__ float g_wor[NV*DD];

// ---------------- helpers ----------------
__device__ __forceinline__ float f2tf32(float x) {
    uint32_t r;
    asm("cvt.rna.tf32.f32 %0, %1;" : "=r"(r) : "f"(x));
    return __uint_as_float(r);
}

__device__ __forceinline__ void cp16(void* smem_dst, const void* gmem_src) {
    uint32_t s = (uint32_t)__cvta_generic_to_shared(smem_dst);
    asm volatile("cp.async.cg.shared.global [%0], [%1], 16;" :: "r"(s), "l"(gmem_src));
}

// permutation within each 32-float K block: p(c) = (c&3)*8 + (c>>2)
// inverse: c(p) = (p&7)*4 + (p>>3)

// round hs to tf32 + permute: out[m][kb*32 + p] = tf32(in[m][kb*32 + c(p)])
__global__ __launch_bounds__(256) void round_perm_kernel(
    const float* __restrict__ src, float* __restrict__ dst, int n4, int Kdim)
{
    int idx = blockIdx.x * 256 + threadIdx.x;
    if (idx >= n4) return;
    int q4 = Kdim >> 2;
    int m = idx / q4;
    int q = idx - m * q4;            // float4 index within row
    int kb = q >> 3;
    int j  = q & 7;
    const float* s = src + (long)m * Kdim + kb * 32;
    float4 o;
    // p = 4j+e -> c = ((4j+e)&7)*4 + ((4j+e)>>3)
    int p0 = 4 * j;
    o.x = f2tf32(s[((p0    ) & 7) * 4 + ((p0    ) >> 3)]);
    o.y = f2tf32(s[((p0 + 1) & 7) * 4 + ((p0 + 1) >> 3)]);
    o.z = f2tf32(s[((p0 + 2) & 7) * 4 + ((p0 + 2) >> 3)]);
    o.w = f2tf32(s[((p0 + 3) & 7) * 4 + ((p0 + 3) >> 3)]);
    *(float4*)(dst + (long)m * Kdim + kb * 32 + p0) = o;
}

// transpose + round + permute: W[K][N] -> WT[n][kb*32 + p]
__global__ __launch_bounds__(256) void transpose_perm_kernel(
    const float* __restrict__ W, float* __restrict__ WT, int K, int N)
{
    __shared__ float t[32][33];
    const int tx = threadIdx.x;       // 0..31
    const int ty = threadIdx.y;       // 0..7
    const int n0 = blockIdx.x * 32;
    const int k0 = blockIdx.y * 32;
#pragma unroll
    for (int i = 0; i < 4; i++)
        t[ty + 8*i][tx] = W[(long)(k0 + ty + 8*i) * N + n0 + tx];
    __syncthreads();
    // one float4 per thread: n = n0+tx, positions p = 4*ty .. 4*ty+3
    int p0 = 4 * ty;
    float4 o;
    o.x = f2tf32(t[((p0    ) & 7) * 4 + ((p0    ) >> 3)][tx]);
    o.y = f2tf32(t[((p0 + 1) & 7) * 4 + ((p0 + 1) >> 3)][tx]);
    o.z = f2tf32(t[((p0 + 2) & 7) * 4 + ((p0 + 2) >> 3)][tx]);
    o.w = f2tf32(t[((p0 + 3) & 7) * 4 + ((p0 + 3) >> 3)][tx]);
    *(float4*)(WT + (long)(n0 + tx) * K + k0 + p0) = o;
}

// ---------------- tf32 mma.sync GEMM v2 ----------------
// C = act(A'[M,K] @ BT'[N,K]^T), A'/BT' in permuted tf32 layout.
// BM=BN=128, BK=32, 256 threads (8 warps, 64x32 warp tiles), 3-stage cp.async.
#define STAGE_BYTES 32768          // 16KB A + 16KB B
#define GSM_TOTAL (3 * STAGE_BYTES)

template<bool SILU>
__global__ __launch_bounds__(256, 1) void tf32gemm2_kernel(
    const float* __restrict__ A, const float* __restrict__ BT,
    float* __restrict__ C, int M, int N, int K)
{
    extern __shared__ char smem[];
    const int tid  = threadIdx.x;
    const int warp = tid >> 5;
    const int lane = tid & 31;
    const int g    = lane >> 2;          // 0..7
    const int tig  = lane & 3;           // 0..3
    const int wm   = (warp >> 2) * 64;   // 0 or 64
    const int wn   = (warp & 3) * 32;    // 0,32,64,96
    const int bm   = blockIdx.y * 128;
    const int bn   = blockIdx.x * 128;
    const int NIT  = K >> 5;

    float c[4][4][4];
#pragma unroll
    for (int mt = 0; mt < 4; mt++)
#pragma unroll
        for (int nt = 0; nt < 4; nt++)
#pragma unroll
            for (int r = 0; r < 4; r++) c[mt][nt][r] = 0.f;

    auto fill = [&](int t) {
        char* As = smem + (t % 3) * STAGE_BYTES;
        char* Bs = As + 16384;
        const int kbase = t << 5;
#pragma unroll
        for (int i = 0; i < 4; i++) {
            int idx = tid + i * 256;         // 0..1023
            int row = idx >> 3;              // 0..127
            int j   = idx & 7;               // chunk
            int slot = j ^ (row & 7);
            cp16(As + row * 128 + slot * 16, A  + (long)(bm + row) * K + kbase + j * 4);
            cp16(Bs + row * 128 + slot * 16, BT + (long)(bn + row) * K + kbase + j * 4);
        }
        asm volatile("cp.async.commit_group;");
    };

    fill(0); fill(1); fill(2);

    for (int t = 0; t < NIT; t++) {
        int rem = NIT - 1 - t;            // remaining after this
        if (rem >= 2)      asm volatile("cp.async.wait_group 2;");
        else if (rem == 1) asm volatile("cp.async.wait_group 1;");
        else               asm volatile("cp.async.wait_group 0;");
        __syncthreads();

        const char* As = smem + (t % 3) * STAGE_BYTES;
        const char* Bs = As + 16384;

#pragma unroll
        for (int half = 0; half < 2; half++) {
            const int ca = 2 * tig + half;
            float4 ag[4], ah[4], bv[4];
#pragma unroll
            for (int mt = 0; mt < 4; mt++) {
                int r1 = wm + mt * 16 + g;
                ag[mt] = *(const float4*)(As + r1 * 128 + ((ca ^ (r1 & 7)) << 4));
                int r2 = r1 + 8;
                ah[mt] = *(const float4*)(As + r2 * 128 + ((ca ^ (r2 & 7)) << 4));
            }
#pragma unroll
            for (int nt = 0; nt < 4; nt++) {
                int rn = wn + nt * 8 + g;
                bv[nt] = *(const float4*)(Bs + rn * 128 + ((ca ^ (rn & 7)) << 4));
            }
            const float* agf; const float* ahf; const float* bvf;
#pragma unroll
            for (int s = 0; s < 2; s++) {
#pragma unroll
                for (int mt = 0; mt < 4; mt++) {
                    agf = (const float*)&ag[mt];
                    ahf = (const float*)&ah[mt];
                    uint32_t a0 = __float_as_uint(agf[2*s]);
                    uint32_t a1 = __float_as_uint(ahf[2*s]);
                    uint32_t a2 = __float_as_uint(agf[2*s+1]);
                    uint32_t a3 = __float_as_uint(ahf[2*s+1]);
#pragma unroll
                    for (int nt = 0; nt < 4; nt++) {
                        bvf = (const float*)&bv[nt];
                        uint32_t b0 = __float_as_uint(bvf[2*s]);
                        uint32_t b1 = __float_as_uint(bvf[2*s+1]);
                        asm volatile(
                            "mma.sync.aligned.m16n8k8.row.col.f32.tf32.tf32.f32 "
                            "{%0,%1,%2,%3}, {%4,%5,%6,%7}, {%8,%9}, {%0,%1,%2,%3};"
                            : "+f"(c[mt][nt][0]), "+f"(c[mt][nt][1]),
                              "+f"(c[mt][nt][2]), "+f"(c[mt][nt][3])
                            : "r"(a0), "r"(a1), "r"(a2), "r"(a3),
                              "r"(b0), "r"(b1));
                    }
                }
            }
        }
        __syncthreads();
        if (t + 3 < NIT) fill(t + 3);
    }

    // epilogue
#pragma unroll
    for (int mt = 0; mt < 4; mt++) {
        int r0 = bm + wm + mt * 16 + g;
#pragma unroll
        for (int nt = 0; nt < 4; nt++) {
            int col = bn + wn + nt * 8 + tig * 2;
            float x0 = c[mt][nt][0], x1 = c[mt][nt][1];
            float x2 = c[mt][nt][2], x3 = c[mt][nt][3];
            if (SILU) {
                x0 = x0 / (1.f + __expf(-x0));
                x1 = x1 / (1.f + __expf(-x1));
                x2 = x2 / (1.f + __expf(-x2));
                x3 = x3 / (1.f + __expf(-x3));
            }
            *(float2*)(C + (long)r0 * N + col)       = make_float2(x0, x1);
            *(float2*)(C + (long)(r0 + 8) * N + col) = make_float2(x2, x3);
        }
    }
}

// ---------------- fused low-rank stage 1: both gates, hs read once ----------
__global__ __launch_bounds__(256) void lowrank1_fused_kernel(
    const float* __restrict__ A, const float* __restrict__ W1,
    const float* __restrict__ W2, float* __restrict__ R1,
    float* __restrict__ R2, int K)
{
    const int warp = threadIdx.x >> 5;
    const int lane = threadIdx.x & 31;
    const int m = blockIdx.x * 8 + warp;
    const float* ap = A + (long)m * K;

    float acc1[16], acc2[16];
#pragma unroll
    for (int n = 0; n < 16; n++) { acc1[n] = 0.f; acc2[n] = 0.f; }

    for (int k = lane; k < K; k += 32) {
        float a = ap[k];
        const float4* w1 = (const float4*)(W1 + (long)k * 16);
        const float4* w2 = (const float4*)(W2 + (long)k * 16);
#pragma unroll
        for (int q = 0; q < 4; q++) {
            float4 u = w1[q];
            acc1[q*4+0] += a * u.x; acc1[q*4+1] += a * u.y;
            acc1[q*4+2] += a * u.z; acc1[q*4+3] += a * u.w;
            float4 v = w2[q];
            acc2[q*4+0] += a * v.x; acc2[q*4+1] += a * v.y;
            acc2[q*4+2] += a * v.z; acc2[q*4+3] += a * v.w;
        }
    }
#pragma unroll
    for (int n = 0; n < 16; n++) {
        float v = acc1[n];
        v += __shfl_xor_sync(0xffffffffu, v, 16);
        v += __shfl_xor_sync(0xffffffffu, v, 8);
        v += __shfl_xor_sync(0xffffffffu, v, 4);
        v += __shfl_xor_sync(0xffffffffu, v, 2);
        v += __shfl_xor_sync(0xffffffffu, v, 1);
        if (lane == 0) R1[(long)m * 16 + n] = v;
        float w = acc2[n];
        w += __shfl_xor_sync(0xffffffffu, w, 16);
        w += __shfl_xor_sync(0xffffffffu, w, 8);
        w += __shfl_xor_sync(0xffffffffu, w, 4);
        w += __shfl_xor_sync(0xffffffffu, w, 2);
        w += __shfl_xor_sync(0xffffffffu, w, 1);
        if (lane == 0) R2[(long)m * 16 + n] = w;
    }
}

// ---------------- low-rank stage 2: Out = act(R[M,16] @ W2[16,N] + b) --------
__global__ __launch_bounds__(256) void lowrank2_kernel(
    const float* __restrict__ Rt, const float* __restrict__ W2,
    const float* __restrict__ bias, float* __restrict__ Out,
    int NOUT, int mode)
{
    int idx = blockIdx.x * 256 + threadIdx.x;
    int m = idx / NOUT;
    int n = idx - m * NOUT;
    const float* r = Rt + (long)m * 16;
    float acc = bias[n];
#pragma unroll
    for (int j = 0; j < 16; j++) acc += r[j] * W2[(long)j * NOUT + n];
    if (mode) {
        float x = acc;
        float ls = (x >= 0.f) ? -log1pf(__expf(-x)) : (x - log1pf(__expf(x)));
        acc = ls * GLN_INV;
    }
    Out[idx] = acc;
}

// ---------------- GLA chunked recurrence ----------------
#define OFF_Q  0
#define OFF_K  4160
#define OFF_A  8320
#define OFF_V  12480
#define OFF_S  14592
#define OFF_GL 16704
#define SM_FLOATS 16768
#define SM_BYTES  (SM_FLOATS * 4)

__global__ __launch_bounds__(256) void gla_kernel(
    const float* __restrict__ Q, const float* __restrict__ Kx,
    const float* __restrict__ V, const float* __restrict__ GK,
    float* __restrict__ O)
{
    extern __shared__ float sm[];
    float* sq  = sm + OFF_Q;
    float* sk  = sm + OFF_K;
    float* sA  = sm + OFF_A;
    float* sv  = sm + OFF_V;
    float* sS  = sm + OFF_S;
    float* sGl = sm + OFF_GL;

    const int tid = threadIdx.x;
    const int s  = blockIdx.x & 3;
    const int bh = blockIdx.x >> 2;
    const int h  = bh & 15;
    const int b  = bh >> 4;
    const int e0 = s * 32;

    const int cb = tid & 63;
    const int eg = tid >> 6;

    for (int i = tid; i < 64 * 33; i += 256) sS[i] = 0.f;

    for (int ch = 0; ch < NCC; ch++) {
        __syncthreads();
        const long base = ((long)(b * TT + ch * 64) * HH + h);
        const float* qp  = Q  + base * DKq;
        const float* kp  = Kx + base * DKq;
        const float* gp  = GK + base * DKq;
        const float* vp  = V  + base * DVv + e0;

#pragma unroll
        for (int w = 0; w < 4; w++) {
            int f = w * 256 + tid;
            int c = f >> 4;
            int dq = (f & 15) << 2;
            float4 a4 = *(const float4*)(qp + (long)c * 1024 + dq);
            sq[c*65+dq]=a4.x; sq[c*65+dq+1]=a4.y; sq[c*65+dq+2]=a4.z; sq[c*65+dq+3]=a4.w;
            float4 b4 = *(const float4*)(kp + (long)c * 1024 + dq);
            sk[c*65+dq]=b4.x; sk[c*65+dq+1]=b4.y; sk[c*65+dq+2]=b4.z; sk[c*65+dq+3]=b4.w;
            float4 g4 = *(const float4*)(gp + (long)c * 1024 + dq);
            sA[c*65+dq]=g4.x; sA[c*65+dq+1]=g4.y; sA[c*65+dq+2]=g4.z; sA[c*65+dq+3]=g4.w;
        }
#pragma unroll
        for (int w = 0; w < 2; w++) {
            int f = w * 256 + tid;
            int c = f >> 3;
            int eq = (f & 7) << 2;
            float4 v4 = *(const float4*)(vp + (long)c * 2048 + eq);
            sv[c*33+eq]=v4.x; sv[c*33+eq+1]=v4.y; sv[c*33+eq+2]=v4.z; sv[c*33+eq+3]=v4.w;
        }
        __syncthreads();

        if (tid < 64) {
            int d = tid;
            float acc = 0.f;
            for (int c = 0; c < 64; c++) {
                acc += sA[c*65 + d];
                sA[c*65 + d] = acc;
            }
            sGl[d] = acc;
        }
        __syncthreads();

#pragma unroll
        for (int w = 0; w < 16; w++) {
            int f = w * 256 + tid;
            int c = f >> 6;
            int d = f & 63;
            float G = sA[c*65 + d];
            sq[c*65 + d] *= __expf(G) * 0.125f;
            sk[c*65 + d] *= __expf(-G);
        }
        if (tid < 64) sGl[tid] = __expf(sGl[tid]);
        __syncthreads();

        float o_r[8];
#pragma unroll
        for (int j = 0; j < 8; j++) o_r[j] = 0.f;
        {
            const int c = cb;
#pragma unroll 4
            for (int d = 0; d < 64; d++) {
                float qv = sq[c*65 + d];
                const float* Srow = &sS[d*33 + eg*8];
#pragma unroll
                for (int j = 0; j < 8; j++) o_r[j] += qv * Srow[j];
            }
        }
        {
            const int c = cb;
            const int jbase = eg * 16;
            float a[16];
#pragma unroll
            for (int jj = 0; jj < 16; jj++) a[jj] = 0.f;
#pragma unroll 2
            for (int d = 0; d < 64; d++) {
                float qv = sq[c*65 + d];
#pragma unroll
                for (int jj = 0; jj < 16; jj++)
                    a[jj] += qv * sk[(jbase + jj)*65 + d];
            }
#pragma unroll
            for (int jj = 0; jj < 16; jj++)
                sA[c*65 + jbase + jj] = (jbase + jj <= c) ? a[jj] : 0.f;
        }
        __syncthreads();

        {
            const int c = cb;
            for (int j64 = 0; j64 <= c; j64++) {
                float a = sA[c*65 + j64];
                const float* vr = &sv[j64*33 + eg*8];
#pragma unroll
                for (int j = 0; j < 8; j++) o_r[j] += a * vr[j];
            }
            float* op = O + (base + (long)c * HH) * DVv + e0 + eg * 8;
            float4 w0 = make_float4(o_r[0], o_r[1], o_r[2], o_r[3]);
            float4 w1 = make_float4(o_r[4], o_r[5], o_r[6], o_r[7]);
            *(float4*)(op)     = w0;
            *(float4*)(op + 4) = w1;
        }
        {
            const int d = cb;
            float* Srow = &sS[d*33 + eg*8];
            float acc[8];
#pragma unroll
            for (int j = 0; j < 8; j++) acc[j] = Srow[j];
#pragma unroll 4
            for (int c64 = 0; c64 < 64; c64++) {
                float kv = sk[c64*65 + d];
                const float* vr = &sv[c64*33 + eg*8];
#pragma unroll
                for (int j = 0; j < 8; j++) acc[j] += kv * vr[j];
            }
            float eGl = sGl[d];
#pragma unroll
            for (int j = 0; j < 8; j++) Srow[j] = acc[j] * eGl;
        }
    }
}

// ---------------- RMS norm + sigmoid gate, in-place tf32 + permuted ----------
// Writes each row back in the permuted-32-block layout for the Wo GEMM.
__global__ __launch_bounds__(256) void rmsgate_kernel(
    float* __restrict__ O, const float* __restrict__ G,
    const float* __restrict__ gw)
{
    int row = blockIdx.x * 8 + (threadIdx.x >> 5);   // (b*T+t)*H + h
    int lane = threadIdx.x & 31;
    long basei = (long)row * 128 + lane * 4;
    float4 o4 = *(float4*)&O[basei];
    float ss = o4.x*o4.x + o4.y*o4.y + o4.z*o4.z + o4.w*o4.w;
    ss += __shfl_xor_sync(0xffffffffu, ss, 16);
    ss += __shfl_xor_sync(0xffffffffu, ss, 8);
    ss += __shfl_xor_sync(0xffffffffu, ss, 4);
    ss += __shfl_xor_sync(0xffffffffu, ss, 2);
    ss += __shfl_xor_sync(0xffffffffu, ss, 1);
    float rr = rsqrtf(ss * (1.f / 128.f) + EPSL);
    float4 g4 = *(const float4*)&G[basei];
    float4 w4 = *(const float4*)&gw[lane * 4];
    float r0 = f2tf32(o4.x * rr * w4.x / (1.f + __expf(-g4.x)));
    float r1 = f2tf32(o4.y * rr * w4.y / (1.f + __expf(-g4.y)));
    float r2 = f2tf32(o4.z * rr * w4.z / (1.f + __expf(-g4.z)));
    float r3 = f2tf32(o4.w * rr * w4.w / (1.f + __expf(-g4.w)));
    // permuted scatter: m_row = row>>4, h = row&15
    // kb = h*4 + (lane>>3), position p = i*8 + (lane&7)
    long obase = (long)(row >> 4) * 2048 + ((row & 15) * 4 + (lane >> 3)) * 32 + (lane & 7);
    O[obase + 0 ] = r0;
    O[obase + 8 ] = r1;
    O[obase + 16] = r2;
    O[obase + 24] = r3;
}

// ---------------- launch ----------------
extern "C" void kernel_launch(void* const* d_in, const int* in_sizes, int n_in,
                              void* d_out, int out_size)
{
    const float* hs    = (const float*)d_in[0];
    const float* Wq    = (const float*)d_in[1];
    const float* Wk    = (const float*)d_in[2];
    const float* Wv    = (const float*)d_in[3];
    const float* Wgk1  = (const float*)d_in[4];
    const float* Wgk2  = (const float*)d_in[5];
    const float* bgk2  = (const float*)d_in[6];
    const float* Wg1   = (const float*)d_in[7];
    const float* Wg2   = (const float*)d_in[8];
    const float* bg2   = (const float*)d_in[9];
    const float* Wo    = (const float*)d_in[10];
    const float* gnw   = (const float*)d_in[11];
    float* out = (float*)d_out;

    float *pq, *pk, *pv, *pgk, *pr1, *pr2, *pg, *po;
    float *phsr, *pwqr, *pwkr, *pwvr, *pwor;
    cudaGetSymbolAddress((void**)&pq,  g_q);
    cudaGetSymbolAddress((void**)&pk,  g_k);
    cudaGetSymbolAddress((void**)&pv,  g_v);
    cudaGetSymbolAddress((void**)&pgk, g_gk);
    cudaGetSymbolAddress((void**)&pr1, g_r1);
    cudaGetSymbolAddress((void**)&pr2, g_r2);
    cudaGetSymbolAddress((void**)&pg,  g_g);
    cudaGetSymbolAddress((void**)&po,  g_o);
    cudaGetSymbolAddress((void**)&phsr, g_hsr);
    cudaGetSymbolAddress((void**)&pwqr, g_wqr);
    cudaGetSymbolAddress((void**)&pwkr, g_wkr);
    cudaGetSymbolAddress((void**)&pwvr, g_wvr);
    cudaGetSymbolAddress((void**)&pwor, g_wor);

    cudaFuncSetAttribute(tf32gemm2_kernel<true>,  cudaFuncAttributeMaxDynamicSharedMemorySize, GSM_TOTAL);
    cudaFuncSetAttribute(tf32gemm2_kernel<false>, cudaFuncAttributeMaxDynamicSharedMemorySize, GSM_TOTAL);
    cudaFuncSetAttribute(gla_kernel, cudaFuncAttributeMaxDynamicSharedMemorySize, SM_BYTES);

    // round+permute hs
    round_perm_kernel<<<(MM*DD/4 + 255)/256, 256>>>(hs, phsr, MM*DD/4, DD);
    // transpose+round+permute weights -> [N][K]
    {
        dim3 blk(32, 8);
        transpose_perm_kernel<<<dim3(NQK/32, DD/32), blk>>>(Wq, pwqr, DD, NQK);
        transpose_perm_kernel<<<dim3(NQK/32, DD/32), blk>>>(Wk, pwkr, DD, NQK);
        transpose_perm_kernel<<<dim3(NV/32,  DD/32), blk>>>(Wv, pwvr, DD, NV);
        transpose_perm_kernel<<<dim3(DD/32,  NV/32), blk>>>(Wo, pwor, NV, DD);
    }
    // projections with silu
    {
        dim3 grid(NQK / 128, MM / 128);
        tf32gemm2_kernel<true><<<grid, 256, GSM_TOTAL>>>(phsr, pwqr, pq, MM, NQK, DD);
        tf32gemm2_kernel<true><<<grid, 256, GSM_TOTAL>>>(phsr, pwkr, pk, MM, NQK, DD);
    }
    {
        dim3 grid(NV / 128, MM / 128);
        tf32gemm2_kernel<true><<<grid, 256, GSM_TOTAL>>>(phsr, pwvr, pv, MM, NV, DD);
    }
    // fused low-rank stage 1 (hs read once), then stage 2 per gate
    lowrank1_fused_kernel<<<MM / 8, 256>>>(hs, Wgk1, Wg1, pr1, pr2, DD);
    lowrank2_kernel<<<(MM * NQK) / 256, 256>>>(pr1, Wgk2, bgk2, pgk, NQK, 1);
    lowrank2_kernel<<<(MM * NV) / 256, 256>>>(pr2, Wg2, bg2, pg, NV, 0);

    // chunked GLA
    gla_kernel<<<BB * HH * 4, 256, SM_BYTES>>>(pq, pk, pv, pgk, po);

    // rms norm + gate (writes permuted tf32 layout for the Wo GEMM)
    rmsgate_kernel<<<(MM * HH) / 8, 256>>>(po, pg, gnw);

    // output projection
    {
        dim3 grid(DD / 128, MM / 128);
        tf32gemm2_kernel<false><<<grid, 256, GSM_TOTAL>>>(po, pwor, out, MM, DD, NV);
    }
    (void)in_sizes; (void)n_in; (void)out_size;
}

// round 7
// speedup vs baseline: 1.5949x; 1.5949x over previous
#include <cuda_runtime.h>
#include <cuda_bf16.h>
#include <math.h>
#include <stdint.h>

// Problem constants
#define BB 2
#define TT 2048
#define DD 2048
#define HH 16
#define DKq 64
#define DVv 128
#define RR 16
#define CC 64
#define NCC 32
#define MM (BB*TT)          // 4096
#define NQK (HH*DKq)        // 1024
#define NV  (HH*DVv)        // 2048
#define GLN_INV (1.0f/16.0f)
#define EPSL 1e-5f

// ---------------- scratch (device globals, no allocs allowed) ----------------
__device__ float g_q [MM*NQK];
__device__ float g_k [MM*NQK];
__device__ float g_v [MM*NV];
__device__ float g_gk[MM*NQK];
__device__ float g_r1[MM*RR];
__device__ float g_r2[MM*RR];
__device__ float g_g [MM*NV];
__device__ float g_o [MM*NV];
__device__ float g_hsr[MM*DD];     // tf32-rounded hs
__device__ float g_wqr[DD*NQK];    // weights rounded (original [K][N] layout)
__device__ float g_wkr[DD*NQK];
__device__ float g_wvr[DD*NV];
__device__ float g_wor[NV*DD];

// ---------------- helpers ----------------
__device__ __forceinline__ float f2tf32(float x) {
    uint32_t r;
    asm("cvt.rna.tf32.f32 %0, %1;" : "=r"(r) : "f"(x));
    return __uint_as_float(r);
}

__device__ __forceinline__ void cp16(void* smem_dst, const void* gmem_src) {
    uint32_t s = (uint32_t)__cvta_generic_to_shared(smem_dst);
    asm volatile("cp.async.cg.shared.global [%0], [%1], 16;" :: "r"(s), "l"(gmem_src));
}

// elementwise rna-round to tf32 (copy)
__global__ __launch_bounds__(256) void round_tf32_kernel(
    const float* __restrict__ src, float* __restrict__ dst, int n4)
{
    int i = blockIdx.x * 256 + threadIdx.x;
    if (i < n4) {
        float4 v = ((const float4*)src)[i];
        v.x = f2tf32(v.x); v.y = f2tf32(v.y);
        v.z = f2tf32(v.z); v.w = f2tf32(v.w);
        ((float4*)dst)[i] = v;
    }
}

// ---------------- tf32 mma.sync GEMM v3 ----------------
// C = act(A[M,K] @ W[K,N]). BM=128, BN=256, BK=32.
// 512 threads (16 warps), warp tile 32x64, 3-stage cp.async ring.
// Smem: As[m][k] stride 36 (conflict-free scalar frag loads: bank 4g+tig),
//       Bs[k][n] stride 264 (bank 8*tig+g). Both proven conflict-free (R2).
#define GA_STRIDE 36
#define GB_STRIDE 264
#define GSM_A (128*GA_STRIDE)            // 4608 floats
#define GSM_B (32*GB_STRIDE)             // 8448 floats
#define STAGE_FLOATS (GSM_A + GSM_B)     // 13056
#define GSTAGES 3
#define GSM_BYTES (GSTAGES*STAGE_FLOATS*4)   // 156672

template<bool SILU>
__global__ __launch_bounds__(512, 1) void tf32gemm3_kernel(
    const float* __restrict__ A, const float* __restrict__ W,
    float* __restrict__ C, int M, int N, int K)
{
    extern __shared__ float sm[];
    const int tid  = threadIdx.x;
    const int warp = tid >> 5;
    const int lane = tid & 31;
    const int g    = lane >> 2;          // 0..7
    const int tig  = lane & 3;           // 0..3
    const int wm   = (warp >> 2) * 32;   // 0,32,64,96
    const int wn   = (warp & 3) * 64;    // 0,64,128,192
    const int bm   = blockIdx.y * 128;
    const int bn   = blockIdx.x * 256;
    const int NIT  = K >> 5;

    float c[2][8][4];
#pragma unroll
    for (int mt = 0; mt < 2; mt++)
#pragma unroll
        for (int nt = 0; nt < 8; nt++)
#pragma unroll
            for (int r = 0; r < 4; r++) c[mt][nt][r] = 0.f;

    auto fill = [&](int t) {
        float* As = sm + (t % 3) * STAGE_FLOATS;
        float* Bs = As + GSM_A;
        const int kbase = t << 5;
        // A tile: 128 rows x 32 floats = 1024 float4, 2 per thread
#pragma unroll
        for (int i = 0; i < 2; i++) {
            int idx = tid + i * 512;         // 0..1023
            int row = idx >> 3;              // 0..127
            int c4  = idx & 7;
            cp16(&As[row * GA_STRIDE + c4 * 4],
                 A + (long)(bm + row) * K + kbase + c4 * 4);
        }
        // B tile: 32 rows x 256 floats = 2048 float4, 4 per thread
#pragma unroll
        for (int i = 0; i < 4; i++) {
            int idx  = tid + i * 512;        // 0..2047
            int krow = idx >> 6;             // 0..31
            int c4   = idx & 63;
            cp16(&Bs[krow * GB_STRIDE + c4 * 4],
                 W + (long)(kbase + krow) * N + bn + c4 * 4);
        }
        asm volatile("cp.async.commit_group;");
    };

    fill(0); fill(1); fill(2);

    for (int t = 0; t < NIT; t++) {
        int rem = NIT - 1 - t;
        if (rem >= 2)      asm volatile("cp.async.wait_group 2;");
        else if (rem == 1) asm volatile("cp.async.wait_group 1;");
        else               asm volatile("cp.async.wait_group 0;");
        __syncthreads();

        const float* Ab = sm + (t % 3) * STAGE_FLOATS;
        const float* Bb = Ab + GSM_A;

#pragma unroll
        for (int ks = 0; ks < 4; ks++) {
            uint32_t a[2][4];
#pragma unroll
            for (int mt = 0; mt < 2; mt++) {
                const float* ap = Ab + (wm + mt * 16 + g) * GA_STRIDE + ks * 8;
                a[mt][0] = __float_as_uint(ap[tig]);
                a[mt][1] = __float_as_uint(ap[8 * GA_STRIDE + tig]);
                a[mt][2] = __float_as_uint(ap[tig + 4]);
                a[mt][3] = __float_as_uint(ap[8 * GA_STRIDE + tig + 4]);
            }
            uint32_t b[8][2];
#pragma unroll
            for (int nt = 0; nt < 8; nt++) {
                const float* bp = Bb + (ks * 8 + tig) * GB_STRIDE + wn + nt * 8 + g;
                b[nt][0] = __float_as_uint(bp[0]);
                b[nt][1] = __float_as_uint(bp[4 * GB_STRIDE]);
            }
#pragma unroll
            for (int mt = 0; mt < 2; mt++)
#pragma unroll
                for (int nt = 0; nt < 8; nt++) {
                    asm volatile(
                        "mma.sync.aligned.m16n8k8.row.col.f32.tf32.tf32.f32 "
                        "{%0,%1,%2,%3}, {%4,%5,%6,%7}, {%8,%9}, {%0,%1,%2,%3};"
                        : "+f"(c[mt][nt][0]), "+f"(c[mt][nt][1]),
                          "+f"(c[mt][nt][2]), "+f"(c[mt][nt][3])
                        : "r"(a[mt][0]), "r"(a[mt][1]), "r"(a[mt][2]), "r"(a[mt][3]),
                          "r"(b[nt][0]), "r"(b[nt][1]));
                }
        }
        __syncthreads();
        if (t + 3 < NIT) fill(t + 3);
    }

    // epilogue
#pragma unroll
    for (int mt = 0; mt < 2; mt++) {
        int r0 = bm + wm + mt * 16 + g;
#pragma unroll
        for (int nt = 0; nt < 8; nt++) {
            int col = bn + wn + nt * 8 + tig * 2;
            float x0 = c[mt][nt][0], x1 = c[mt][nt][1];
            float x2 = c[mt][nt][2], x3 = c[mt][nt][3];
            if (SILU) {
                x0 = x0 / (1.f + __expf(-x0));
                x1 = x1 / (1.f + __expf(-x1));
                x2 = x2 / (1.f + __expf(-x2));
                x3 = x3 / (1.f + __expf(-x3));
            }
            *(float2*)(C + (long)r0 * N + col)       = make_float2(x0, x1);
            *(float2*)(C + (long)(r0 + 8) * N + col) = make_float2(x2, x3);
        }
    }
}

// ---------------- fused low-rank stage 1: both gates, hs read once ----------
__global__ __launch_bounds__(256) void lowrank1_fused_kernel(
    const float* __restrict__ A, const float* __restrict__ W1,
    const float* __restrict__ W2, float* __restrict__ R1,
    float* __restrict__ R2, int K)
{
    const int warp = threadIdx.x >> 5;
    const int lane = threadIdx.x & 31;
    const int m = blockIdx.x * 8 + warp;
    const float* ap = A + (long)m * K;

    float acc1[16], acc2[16];
#pragma unroll
    for (int n = 0; n < 16; n++) { acc1[n] = 0.f; acc2[n] = 0.f; }

    for (int k = lane; k < K; k += 32) {
        float a = ap[k];
        const float4* w1 = (const float4*)(W1 + (long)k * 16);
        const float4* w2 = (const float4*)(W2 + (long)k * 16);
#pragma unroll
        for (int q = 0; q < 4; q++) {
            float4 u = w1[q];
            acc1[q*4+0] += a * u.x; acc1[q*4+1] += a * u.y;
            acc1[q*4+2] += a * u.z; acc1[q*4+3] += a * u.w;
            float4 v = w2[q];
            acc2[q*4+0] += a * v.x; acc2[q*4+1] += a * v.y;
            acc2[q*4+2] += a * v.z; acc2[q*4+3] += a * v.w;
        }
    }
#pragma unroll
    for (int n = 0; n < 16; n++) {
        float v = acc1[n];
        v += __shfl_xor_sync(0xffffffffu, v, 16);
        v += __shfl_xor_sync(0xffffffffu, v, 8);
        v += __shfl_xor_sync(0xffffffffu, v, 4);
        v += __shfl_xor_sync(0xffffffffu, v, 2);
        v += __shfl_xor_sync(0xffffffffu, v, 1);
        if (lane == 0) R1[(long)m * 16 + n] = v;
        float w = acc2[n];
        w += __shfl_xor_sync(0xffffffffu, w, 16);
        w += __shfl_xor_sync(0xffffffffu, w, 8);
        w += __shfl_xor_sync(0xffffffffu, w, 4);
        w += __shfl_xor_sync(0xffffffffu, w, 2);
        w += __shfl_xor_sync(0xffffffffu, w, 1);
        if (lane == 0) R2[(long)m * 16 + n] = w;
    }
}

// ---------------- low-rank stage 2: Out = act(R[M,16] @ W2[16,N] + b) --------
__global__ __launch_bounds__(256) void lowrank2_kernel(
    const float* __restrict__ Rt, const float* __restrict__ W2,
    const float* __restrict__ bias, float* __restrict__ Out,
    int NOUT, int mode)
{
    int idx = blockIdx.x * 256 + threadIdx.x;
    int m = idx / NOUT;
    int n = idx - m * NOUT;
    const float* r = Rt + (long)m * 16;
    float acc = bias[n];
#pragma unroll
    for (int j = 0; j < 16; j++) acc += r[j] * W2[(long)j * NOUT + n];
    if (mode) {
        float x = acc;
        float ls = (x >= 0.f) ? -log1pf(__expf(-x)) : (x - log1pf(__expf(x)));
        acc = ls * GLN_INV;
    }
    Out[idx] = acc;
}

// ---------------- GLA chunked recurrence ----------------
#define OFF_Q  0
#define OFF_K  4160
#define OFF_A  8320
#define OFF_V  12480
#define OFF_S  14592
#define OFF_GL 16704
#define SM_FLOATS 16768
#define SM_BYTES  (SM_FLOATS * 4)

__global__ __launch_bounds__(256) void gla_kernel(
    const float* __restrict__ Q, const float* __restrict__ Kx,
    const float* __restrict__ V, const float* __restrict__ GK,
    float* __restrict__ O)
{
    extern __shared__ float sm[];
    float* sq  = sm + OFF_Q;
    float* sk  = sm + OFF_K;
    float* sA  = sm + OFF_A;
    float* sv  = sm + OFF_V;
    float* sS  = sm + OFF_S;
    float* sGl = sm + OFF_GL;

    const int tid = threadIdx.x;
    const int s  = blockIdx.x & 3;
    const int bh = blockIdx.x >> 2;
    const int h  = bh & 15;
    const int b  = bh >> 4;
    const int e0 = s * 32;

    const int cb = tid & 63;
    const int eg = tid >> 6;

    for (int i = tid; i < 64 * 33; i += 256) sS[i] = 0.f;

    for (int ch = 0; ch < NCC; ch++) {
        __syncthreads();
        const long base = ((long)(b * TT + ch * 64) * HH + h);
        const float* qp  = Q  + base * DKq;
        const float* kp  = Kx + base * DKq;
        const float* gp  = GK + base * DKq;
        const float* vp  = V  + base * DVv + e0;

#pragma unroll
        for (int w = 0; w < 4; w++) {
            int f = w * 256 + tid;
            int c = f >> 4;
            int dq = (f & 15) << 2;
            float4 a4 = *(const float4*)(qp + (long)c * 1024 + dq);
            sq[c*65+dq]=a4.x; sq[c*65+dq+1]=a4.y; sq[c*65+dq+2]=a4.z; sq[c*65+dq+3]=a4.w;
            float4 b4 = *(const float4*)(kp + (long)c * 1024 + dq);
            sk[c*65+dq]=b4.x; sk[c*65+dq+1]=b4.y; sk[c*65+dq+2]=b4.z; sk[c*65+dq+3]=b4.w;
            float4 g4 = *(const float4*)(gp + (long)c * 1024 + dq);
            sA[c*65+dq]=g4.x; sA[c*65+dq+1]=g4.y; sA[c*65+dq+2]=g4.z; sA[c*65+dq+3]=g4.w;
        }
#pragma unroll
        for (int w = 0; w < 2; w++) {
            int f = w * 256 + tid;
            int c = f >> 3;
            int eq = (f & 7) << 2;
            float4 v4 = *(const float4*)(vp + (long)c * 2048 + eq);
            sv[c*33+eq]=v4.x; sv[c*33+eq+1]=v4.y; sv[c*33+eq+2]=v4.z; sv[c*33+eq+3]=v4.w;
        }
        __syncthreads();

        if (tid < 64) {
            int d = tid;
            float acc = 0.f;
            for (int c = 0; c < 64; c++) {
                acc += sA[c*65 + d];
                sA[c*65 + d] = acc;
            }
            sGl[d] = acc;
        }
        __syncthreads();

#pragma unroll
        for (int w = 0; w < 16; w++) {
            int f = w * 256 + tid;
            int c = f >> 6;
            int d = f & 63;
            float G = sA[c*65 + d];
            sq[c*65 + d] *= __expf(G) * 0.125f;
            sk[c*65 + d] *= __expf(-G);
        }
        if (tid < 64) sGl[tid] = __expf(sGl[tid]);
        __syncthreads();

        float o_r[8];
#pragma unroll
        for (int j = 0; j < 8; j++) o_r[j] = 0.f;
        {
            const int c = cb;
#pragma unroll 4
            for (int d = 0; d < 64; d++) {
                float qv = sq[c*65 + d];
                const float* Srow = &sS[d*33 + eg*8];
#pragma unroll
                for (int j = 0; j < 8; j++) o_r[j] += qv * Srow[j];
            }
        }
        {
            const int c = cb;
            const int jbase = eg * 16;
            float a[16];
#pragma unroll
            for (int jj = 0; jj < 16; jj++) a[jj] = 0.f;
#pragma unroll 2
            for (int d = 0; d < 64; d++) {
                float qv = sq[c*65 + d];
#pragma unroll
                for (int jj = 0; jj < 16; jj++)
                    a[jj] += qv * sk[(jbase + jj)*65 + d];
            }
#pragma unroll
            for (int jj = 0; jj < 16; jj++)
                sA[c*65 + jbase + jj] = (jbase + jj <= c) ? a[jj] : 0.f;
        }
        __syncthreads();

        {
            const int c = cb;
            for (int j64 = 0; j64 <= c; j64++) {
                float a = sA[c*65 + j64];
                const float* vr = &sv[j64*33 + eg*8];
#pragma unroll
                for (int j = 0; j < 8; j++) o_r[j] += a * vr[j];
            }
            float* op = O + (base + (long)c * HH) * DVv + e0 + eg * 8;
            float4 w0 = make_float4(o_r[0], o_r[1], o_r[2], o_r[3]);
            float4 w1 = make_float4(o_r[4], o_r[5], o_r[6], o_r[7]);
            *(float4*)(op)     = w0;
            *(float4*)(op + 4) = w1;
        }
        {
            const int d = cb;
            float* Srow = &sS[d*33 + eg*8];
            float acc[8];
#pragma unroll
            for (int j = 0; j < 8; j++) acc[j] = Srow[j];
#pragma unroll 4
            for (int c64 = 0; c64 < 64; c64++) {
                float kv = sk[c64*65 + d];
                const float* vr = &sv[c64*33 + eg*8];
#pragma unroll
                for (int j = 0; j < 8; j++) acc[j] += kv * vr[j];
            }
            float eGl = sGl[d];
#pragma unroll
            for (int j = 0; j < 8; j++) Srow[j] = acc[j] * eGl;
        }
    }
}

// ---------------- RMS norm + sigmoid gate (in place, outputs tf32-rounded) ---
__global__ __launch_bounds__(256) void rmsgate_kernel(
    float* __restrict__ O, const float* __restrict__ G,
    const float* __restrict__ gw)
{
    int row = blockIdx.x * 8 + (threadIdx.x >> 5);
    int lane = threadIdx.x & 31;
    long basei = (long)row * 128 + lane * 4;
    float4 o4 = *(float4*)&O[basei];
    float ss = o4.x*o4.x + o4.y*o4.y + o4.z*o4.z + o4.w*o4.w;
    ss += __shfl_xor_sync(0xffffffffu, ss, 16);
    ss += __shfl_xor_sync(0xffffffffu, ss, 8);
    ss += __shfl_xor_sync(0xffffffffu, ss, 4);
    ss += __shfl_xor_sync(0xffffffffu, ss, 2);
    ss += __shfl_xor_sync(0xffffffffu, ss, 1);
    float rr = rsqrtf(ss * (1.f / 128.f) + EPSL);
    float4 g4 = *(const float4*)&G[basei];
    float4 w4 = *(const float4*)&gw[lane * 4];
    o4.x = f2tf32(o4.x * rr * w4.x / (1.f + __expf(-g4.x)));
    o4.y = f2tf32(o4.y * rr * w4.y / (1.f + __expf(-g4.y)));
    o4.z = f2tf32(o4.z * rr * w4.z / (1.f + __expf(-g4.z)));
    o4.w = f2tf32(o4.w * rr * w4.w / (1.f + __expf(-g4.w)));
    *(float4*)&O[basei] = o4;
}

// ---------------- launch ----------------
extern "C" void kernel_launch(void* const* d_in, const int* in_sizes, int n_in,
                              void* d_out, int out_size)
{
    const float* hs    = (const float*)d_in[0];
    const float* Wq    = (const float*)d_in[1];
    const float* Wk    = (const float*)d_in[2];
    const float* Wv    = (const float*)d_in[3];
    const float* Wgk1  = (const float*)d_in[4];
    const float* Wgk2  = (const float*)d_in[5];
    const float* bgk2  = (const float*)d_in[6];
    const float* Wg1   = (const float*)d_in[7];
    const float* Wg2   = (const float*)d_in[8];
    const float* bg2   = (const float*)d_in[9];
    const float* Wo    = (const float*)d_in[10];
    const float* gnw   = (const float*)d_in[11];
    float* out = (float*)d_out;

    float *pq, *pk, *pv, *pgk, *pr1, *pr2, *pg, *po;
    float *phsr, *pwqr, *pwkr, *pwvr, *pwor;
    cudaGetSymbolAddress((void**)&pq,  g_q);
    cudaGetSymbolAddress((void**)&pk,  g_k);
    cudaGetSymbolAddress((void**)&pv,  g_v);
    cudaGetSymbolAddress((void**)&pgk, g_gk);
    cudaGetSymbolAddress((void**)&pr1, g_r1);
    cudaGetSymbolAddress((void**)&pr2, g_r2);
    cudaGetSymbolAddress((void**)&pg,  g_g);
    cudaGetSymbolAddress((void**)&po,  g_o);
    cudaGetSymbolAddress((void**)&phsr, g_hsr);
    cudaGetSymbolAddress((void**)&pwqr, g_wqr);
    cudaGetSymbolAddress((void**)&pwkr, g_wkr);
    cudaGetSymbolAddress((void**)&pwvr, g_wvr);
    cudaGetSymbolAddress((void**)&pwor, g_wor);

    cudaFuncSetAttribute(tf32gemm3_kernel<true>,  cudaFuncAttributeMaxDynamicSharedMemorySize, GSM_BYTES);
    cudaFuncSetAttribute(tf32gemm3_kernel<false>, cudaFuncAttributeMaxDynamicSharedMemorySize, GSM_BYTES);
    cudaFuncSetAttribute(gla_kernel, cudaFuncAttributeMaxDynamicSharedMemorySize, SM_BYTES);

    // tf32 pre-rounding of GEMM operands (weights keep [K][N] layout)
    round_tf32_kernel<<<(MM*DD/4 + 255)/256, 256>>>(hs, phsr, MM*DD/4);
    round_tf32_kernel<<<(DD*NQK/4 + 255)/256, 256>>>(Wq, pwqr, DD*NQK/4);
    round_tf32_kernel<<<(DD*NQK/4 + 255)/256, 256>>>(Wk, pwkr, DD*NQK/4);
    round_tf32_kernel<<<(DD*NV/4 + 255)/256, 256>>>(Wv, pwvr, DD*NV/4);
    round_tf32_kernel<<<(NV*DD/4 + 255)/256, 256>>>(Wo, pwor, NV*DD/4);

    // projections with silu (launch #6 is ncu-captured)
    {
        dim3 grid(NQK / 256, MM / 128);
        tf32gemm3_kernel<true><<<grid, 512, GSM_BYTES>>>(phsr, pwqr, pq, MM, NQK, DD);
        tf32gemm3_kernel<true><<<grid, 512, GSM_BYTES>>>(phsr, pwkr, pk, MM, NQK, DD);
    }
    {
        dim3 grid(NV / 256, MM / 128);
        tf32gemm3_kernel<true><<<grid, 512, GSM_BYTES>>>(phsr, pwvr, pv, MM, NV, DD);
    }
    // fused low-rank stage 1 (hs read once), then stage 2 per gate
    lowrank1_fused_kernel<<<MM / 8, 256>>>(hs, Wgk1, Wg1, pr1, pr2, DD);
    lowrank2_kernel<<<(MM * NQK) / 256, 256>>>(pr1, Wgk2, bgk2, pgk, NQK, 1);
    lowrank2_kernel<<<(MM * NV) / 256, 256>>>(pr2, Wg2, bg2, pg, NV, 0);

    // chunked GLA
    gla_kernel<<<BB * HH * 4, 256, SM_BYTES>>>(pq, pk, pv, pgk, po);

    // rms norm + gate (rounds o to tf32 for the Wo GEMM)
    rmsgate_kernel<<<(MM * HH) / 8, 256>>>(po, pg, gnw);

    // output projection
    {
        dim3 grid(DD / 256, MM / 128);
        tf32gemm3_kernel<false><<<grid, 512, GSM_BYTES>>>(po, pwor, out, MM, DD, NV);
    }
    (void)in_sizes; (void)n_in; (void)out_size;
}